// round 13
// baseline (speedup 1.0000x reference)
#include <cuda_runtime.h>

#define DH 64
#define DIN 128
#define MAXN 100000
#define MAXE 1000000
#define EPSN 1e-5f
#define SLOPE 0.2f
typedef unsigned long long ull;

// ---------------- device scratch (no allocations allowed) ----------------
__device__ float g_xw[MAXN * DH];    // gemm output / gather source
__device__ float g_agg[MAXN * DH];   // aggregated output per layer
__device__ int   g_degi[MAXN];
__device__ int   g_cur[MAXN];
__device__ int   g_off[MAXN];
__device__ int   g_bsum[256];        // raw per-block sums from scan1
__device__ int   g_bscan[256];       // exclusive-scanned (published by fill blk 0)
__device__ float g_dinv[MAXN];
__device__ int2  g_sedge[MAXE];      // (src, coef bits) sorted by dst
__device__ float g_pS1[2048], g_pQ1[2048], g_pS2[2048], g_pQ2[2048]; // [32 slots][64]
__device__ float g_A[DH], g_B[DH];
__device__ float g_Wc[DIN * DH];     // W_in@W1 chunked: [(k>>2)*256 + c*4 + (k&3)]
__device__ float g_bc[DH];           // b_in @ W1
__device__ float g_W2c[DH * DH];     // W2 chunked

// ---------------- packed f32x2 helpers ----------------
#define FMA2(d,a,b)     asm("fma.rn.f32x2 %0, %1, %2, %0;" : "+l"(d) : "l"(a), "l"(b))
#define UNPACK2(l,h,s)  asm("mov.b64 {%0, %1}, %2;" : "=f"(l), "=f"(h) : "l"(s))
#define PACKF2(d,lo,hi) asm("mov.b64 %0, {%1, %2};" : "=l"(d) : "f"(lo), "f"(hi))

// ---------------- weight prep: Wc = W_in@W1 chunked, bc, W2 chunked ----------------
__global__ void __launch_bounds__(256)
wcw2c_kernel(const float* __restrict__ Win, const float* __restrict__ W1,
             const float* __restrict__ b_in, const float* __restrict__ W2) {
    int t = threadIdx.x;
    if (blockIdx.x < 32) {
        __shared__ float sW1[DH * DH];
        for (int i = t; i < DH * DH; i += 256) sW1[i] = W1[i];
        __syncthreads();
        int o = blockIdx.x * 256 + t;            // 8192 outputs
        int i = o >> 6, j = o & 63;
        float s = 0.f;
#pragma unroll 16
        for (int k = 0; k < DH; k++) s += Win[i * DH + k] * sW1[k * DH + j];
        g_Wc[(i >> 2) * 256 + j * 4 + (i & 3)] = s;
        if (o < DH) {
            float b = 0.f;
#pragma unroll 16
            for (int k = 0; k < DH; k++) b += b_in[k] * sW1[k * DH + j];
            g_bc[o] = b;
        }
    } else {
        int o = (blockIdx.x - 32) * 256 + t;     // 4096
        int i = o >> 6, j = o & 63;
        g_W2c[(i >> 2) * 256 + j * 4 + (i & 3)] = W2[o];
    }
}

// ---------------- small utility kernels ----------------
__global__ void zero_kernel(int n) {
    int i = blockIdx.x * blockDim.x + threadIdx.x;
    if (i < n) { g_degi[i] = 0; g_cur[i] = 0; }
    if (i < 2048) {
        g_pS1[i] = 0.f; g_pQ1[i] = 0.f;
        g_pS2[i] = 0.f; g_pQ2[i] = 0.f;
    }
}

__global__ void deg_kernel(const int* __restrict__ dst, int E) {
    int e = blockIdx.x * blockDim.x + threadIdx.x;
    if (e < E) atomicAdd(&g_degi[dst[e]], 1);
}

// shuffle-based block scan -> exclusive offsets + raw block sums (+ dinv fused)
__global__ void __launch_bounds__(1024) scan1_kernel(int n) {
    __shared__ int wsum[32];
    int t = threadIdx.x;
    int lane = t & 31, wid = t >> 5;
    int i = blockIdx.x * 1024 + t;
    int v = (i < n) ? g_degi[i] : 0;
    int x = v;
#pragma unroll
    for (int off = 1; off < 32; off <<= 1) {
        int y = __shfl_up_sync(0xffffffffu, x, off);
        if (lane >= off) x += y;
    }
    if (lane == 31) wsum[wid] = x;
    __syncthreads();
    if (wid == 0) {
        int wv = wsum[lane];
        int wx = wv;
#pragma unroll
        for (int off = 1; off < 32; off <<= 1) {
            int y = __shfl_up_sync(0xffffffffu, wx, off);
            if (lane >= off) wx += y;
        }
        wsum[lane] = wx - wv;
    }
    __syncthreads();
    int incl = x + wsum[wid];
    if (i < n) {
        g_off[i] = incl - v;
        g_dinv[i] = rsqrtf((float)v + 1.0f);
    }
    if (t == 1023) g_bsum[blockIdx.x] = incl;
}

// fill (scan2 folded: every block scans the <=256 raw block sums in smem)
__global__ void __launch_bounds__(256)
fill_kernel(const int* __restrict__ src, const int* __restrict__ dst, int E, int nb) {
    __shared__ int s[256];
    int t = threadIdx.x;
    int v = (t < nb) ? g_bsum[t] : 0;
    s[t] = v; __syncthreads();
#pragma unroll
    for (int off = 1; off < 256; off <<= 1) {
        int tmp = (t >= off) ? s[t - off] : 0;
        __syncthreads();
        s[t] += tmp;
        __syncthreads();
    }
    int ex = s[t] - v;
    __syncthreads();
    s[t] = ex;                 // exclusive scan now resident in smem
    if (blockIdx.x == 0 && t < nb) g_bscan[t] = ex;  // publish for agg
    __syncthreads();

    int e = blockIdx.x * 256 + t;
    if (e >= E) return;
    int d = dst[e], sc = src[e];
    int p = g_off[d] + s[d >> 10] + atomicAdd(&g_cur[d], 1);
    g_sedge[p] = make_int2(sc, __float_as_int(g_dinv[sc] * g_dinv[d]));
}

// ---------------- GEMM: g_xw[n,64] = X[n,K] @ W[K,64] ----------------
// No smem/syncs. Chunked weights; FFMA2 lanes carry adjacent k pair.
// Thread tile: 4 rows x 4 ADJACENT cols (cg*4..+3) -> STG.128 stores.
// MODE 0: X = external arg, W = g_Wc, += g_bc.
// MODE 2: X = leaky(g_A*g_agg+g_B) (GraphNorm1 fused), W = g_W2c.
template<int K, int MODE>
__global__ void __launch_bounds__(256, 3)
gemm_kernel(const float* __restrict__ Xarg, int n) {
    const float* __restrict__ X = (MODE == 0) ? Xarg : g_agg;
    const float* __restrict__ Wp = (MODE == 0) ? g_Wc : g_W2c;
    const int tid = threadIdx.x;
    const int cg = tid & 15, rg = tid >> 4;
    const int r0 = blockIdx.x * 64 + rg * 4;
    const int c0 = cg * 4;

    bool ok[4];
#pragma unroll
    for (int i = 0; i < 4; i++) ok[i] = (r0 + i) < n;

    ull acc[4][4];
#pragma unroll
    for (int i = 0; i < 4; i++)
#pragma unroll
        for (int j = 0; j < 4; j++) acc[i][j] = 0ull;

#pragma unroll 4
    for (int kc = 0; kc < K / 4; kc++) {
        ulonglong2 wv[4];
#pragma unroll
        for (int jj = 0; jj < 4; jj++)
            wv[jj] = *(const ulonglong2*)(Wp + kc * 256 + (c0 + jj) * 4);

        float4 Af, Bf;
        if (MODE == 2) {
            Af = *(const float4*)&g_A[kc * 4];
            Bf = *(const float4*)&g_B[kc * 4];
        }
#pragma unroll
        for (int i = 0; i < 4; i++) {
            ull x01 = 0ull, x23 = 0ull;
            if (ok[i]) {
                if (MODE == 0) {
                    ulonglong2 xv = *(const ulonglong2*)(X + (size_t)(r0 + i) * K + kc * 4);
                    x01 = xv.x; x23 = xv.y;
                } else {
                    float4 xf = *(const float4*)(X + (size_t)(r0 + i) * K + kc * 4);
                    xf.x = Af.x * xf.x + Bf.x; xf.x = fmaxf(xf.x, SLOPE * xf.x);
                    xf.y = Af.y * xf.y + Bf.y; xf.y = fmaxf(xf.y, SLOPE * xf.y);
                    xf.z = Af.z * xf.z + Bf.z; xf.z = fmaxf(xf.z, SLOPE * xf.z);
                    xf.w = Af.w * xf.w + Bf.w; xf.w = fmaxf(xf.w, SLOPE * xf.w);
                    PACKF2(x01, xf.x, xf.y);
                    PACKF2(x23, xf.z, xf.w);
                }
            }
            FMA2(acc[i][0], x01, wv[0].x); FMA2(acc[i][0], x23, wv[0].y);
            FMA2(acc[i][1], x01, wv[1].x); FMA2(acc[i][1], x23, wv[1].y);
            FMA2(acc[i][2], x01, wv[2].x); FMA2(acc[i][2], x23, wv[2].y);
            FMA2(acc[i][3], x01, wv[3].x); FMA2(acc[i][3], x23, wv[3].y);
        }
    }

    float4 bf = make_float4(0.f, 0.f, 0.f, 0.f);
    if (MODE == 0) bf = *(const float4*)&g_bc[c0];
#pragma unroll
    for (int i = 0; i < 4; i++) {
        if (!ok[i]) continue;
        float4 o;
        float lo, hi;
        UNPACK2(lo, hi, acc[i][0]); o.x = lo + hi + bf.x;
        UNPACK2(lo, hi, acc[i][1]); o.y = lo + hi + bf.y;
        UNPACK2(lo, hi, acc[i][2]); o.z = lo + hi + bf.z;
        UNPACK2(lo, hi, acc[i][3]); o.w = lo + hi + bf.w;
        *(float4*)&g_xw[(size_t)(r0 + i) * DH + c0] = o;
    }
}

// ---------------- CSR gather aggregation + fused per-feature stats ----------------
// One full warp per node; lane owns cols {2l, 2l+1}; 4 gathers in flight.
// Block reduces its 8 nodes' outputs into spread float-atomic staging.
template<int L>
__global__ void __launch_bounds__(256)
agg_kernel(const float* __restrict__ bias, int n) {
    __shared__ float sS[8][DH];
    __shared__ float sQ[8][DH];
    int wid = threadIdx.x >> 5;
    int lane = threadIdx.x & 31;
    int w = blockIdx.x * 8 + wid;
    bool active = w < n;
    int j2 = lane * 2;

    float o0 = 0.f, o1 = 0.f;
    if (active) {
        int start = g_off[w] + g_bscan[w >> 10];
        int end = start + g_degi[w];
        float a0 = 0.f, a1 = 0.f, b0 = 0.f, b1 = 0.f;
        float c2 = 0.f, c3 = 0.f, d2_ = 0.f, d3 = 0.f;
        int e = start;
        for (; e + 3 < end; e += 4) {
            int2 p0 = g_sedge[e];
            int2 p1 = g_sedge[e + 1];
            int2 p2 = g_sedge[e + 2];
            int2 p3 = g_sedge[e + 3];
            float2 v0 = *(const float2*)&g_xw[(size_t)p0.x * DH + j2];
            float2 v1 = *(const float2*)&g_xw[(size_t)p1.x * DH + j2];
            float2 v2 = *(const float2*)&g_xw[(size_t)p2.x * DH + j2];
            float2 v3 = *(const float2*)&g_xw[(size_t)p3.x * DH + j2];
            float f0 = __int_as_float(p0.y), f1 = __int_as_float(p1.y);
            float f2 = __int_as_float(p2.y), f3 = __int_as_float(p3.y);
            a0 += f0 * v0.x; a1 += f0 * v0.y;
            b0 += f1 * v1.x; b1 += f1 * v1.y;
            c2 += f2 * v2.x; c3 += f2 * v2.y;
            d2_ += f3 * v3.x; d3 += f3 * v3.y;
        }
        for (; e < end; e++) {
            int2 p = g_sedge[e];
            float2 v = *(const float2*)&g_xw[(size_t)p.x * DH + j2];
            float c = __int_as_float(p.y);
            a0 += c * v.x; a1 += c * v.y;
        }
        a0 += b0 + c2 + d2_;
        a1 += b1 + c3 + d3;

        float d = g_dinv[w];
        float dd = d * d;
        float2 xv = *(const float2*)&g_xw[(size_t)w * DH + j2];
        float2 bb = *(const float2*)&bias[j2];
        o0 = a0 + dd * xv.x + bb.x;
        o1 = a1 + dd * xv.y + bb.y;
        *(float2*)&g_agg[(size_t)w * DH + j2] = make_float2(o0, o1);
    }

    // fused stats: block partial sums -> spread staging
    sS[wid][j2] = o0;      sS[wid][j2 + 1] = o1;
    sQ[wid][j2] = o0 * o0; sQ[wid][j2 + 1] = o1 * o1;
    __syncthreads();
    if (threadIdx.x < DH) {
        int j = threadIdx.x;
        float s = 0.f, q = 0.f;
#pragma unroll
        for (int r = 0; r < 8; r++) { s += sS[r][j]; q += sQ[r][j]; }
        int slot = (blockIdx.x & 31) * DH + j;
        if (L == 1) { atomicAdd(&g_pS1[slot], s); atomicAdd(&g_pQ1[slot], q); }
        else        { atomicAdd(&g_pS2[slot], s); atomicAdd(&g_pQ2[slot], q); }
    }
}

// ---------------- fold GraphNorm into out = A*x + B ----------------
template<int L>
__global__ void finalize_kernel(const float* __restrict__ alpha,
                                const float* __restrict__ gamma,
                                const float* __restrict__ beta, int n) {
    int j = threadIdx.x;
    if (j >= DH) return;
    double S = 0.0, Q = 0.0;
    for (int k = 0; k < 32; k++) {
        if (L == 1) { S += (double)g_pS1[k * DH + j]; Q += (double)g_pQ1[k * DH + j]; }
        else        { S += (double)g_pS2[k * DH + j]; Q += (double)g_pQ2[k * DH + j]; }
    }
    double m = S / (double)n;
    double a = (double)alpha[j];
    double var = Q / (double)n - 2.0 * a * m * m + a * a * m * m;
    float inv = rsqrtf((float)var + EPSN);
    float g = gamma[j] * inv;
    g_A[j] = g;
    g_B[j] = beta[j] - g * (float)(a * m);
}

// out = A*agg + B   (float4)
__global__ void __launch_bounds__(256)
norm_out_kernel(float* __restrict__ out, int total4) {
    int i = blockIdx.x * 256 + threadIdx.x;
    if (i >= total4) return;
    int j = (i * 4) & 63;
    float4 v = *(const float4*)&g_agg[(size_t)i * 4];
    float4 A = *(const float4*)&g_A[j];
    float4 B = *(const float4*)&g_B[j];
    v.x = A.x * v.x + B.x;
    v.y = A.y * v.y + B.y;
    v.z = A.z * v.z + B.z;
    v.w = A.w * v.w + B.w;
    *(float4*)&out[(size_t)i * 4] = v;
}

// ---------------- launcher ----------------
extern "C" void kernel_launch(void* const* d_in, const int* in_sizes, int n_in,
                              void* d_out, int out_size) {
    const float* x    = (const float*)d_in[0];
    const int*   ei   = (const int*)d_in[1];
    const float* W_in = (const float*)d_in[2];
    const float* b_in = (const float*)d_in[3];
    const float* W1   = (const float*)d_in[4];
    const float* b1   = (const float*)d_in[5];
    const float* a1   = (const float*)d_in[6];
    const float* gm1  = (const float*)d_in[7];
    const float* be1  = (const float*)d_in[8];
    const float* W2   = (const float*)d_in[9];
    const float* b2   = (const float*)d_in[10];
    const float* a2   = (const float*)d_in[11];
    const float* gm2  = (const float*)d_in[12];
    const float* be2  = (const float*)d_in[13];
    float* out = (float*)d_out;

    const int n = in_sizes[0] / DIN;
    const int E = in_sizes[1] / 2;
    const int* src = ei;
    const int* dst = ei + E;
    const int total4 = n * DH / 4;
    const int nb = (n + 1023) >> 10;
    const int gemm_blocks = (n + 63) / 64;

    // 0: fused weight prep
    wcw2c_kernel<<<48, 256>>>(W_in, W1, b_in, W2);
    // 1-2: degree
    zero_kernel<<<(n + 255) / 256, 256>>>(n);
    deg_kernel<<<(E + 255) / 256, 256>>>(dst, E);
    // 3: big GEMM (profile slot)
    gemm_kernel<DIN, 0><<<gemm_blocks, 256>>>(x, n);
    // 4-5: CSR build
    scan1_kernel<<<nb, 1024>>>(n);
    fill_kernel<<<(E + 255) / 256, 256>>>(src, dst, E, nb);
    // 6-7: layer 1 aggregate + norm coefficients
    agg_kernel<1><<<(n + 7) / 8, 256>>>(b1, n);
    finalize_kernel<1><<<1, 64>>>(a1, gm1, be1, n);
    // 8: layer 2 GEMM with fused GraphNorm1+LeakyReLU input
    gemm_kernel<DH, 2><<<gemm_blocks, 256>>>(nullptr, n);
    // 9-10: layer 2 aggregate + norm coefficients
    agg_kernel<2><<<(n + 7) / 8, 256>>>(b2, n);
    finalize_kernel<2><<<1, 64>>>(a2, gm2, be2, n);
    // 11: final output
    norm_out_kernel<<<(total4 + 255) / 256, 256>>>(out, total4);
}

// round 15
// speedup vs baseline: 1.8562x; 1.8562x over previous
#include <cuda_runtime.h>

#define DH 64
#define DIN 128
#define MAXN 100000
#define MAXE 1000000
#define EPSN 1e-5f
#define SLOPE 0.2f
typedef unsigned long long ull;

// ---------------- device scratch (no allocations allowed) ----------------
__device__ float g_xw[MAXN * DH];    // gemm output / gather source
__device__ float g_agg[MAXN * DH];   // aggregated output per layer
__device__ int   g_degi[MAXN];
__device__ int   g_cur[MAXN];
__device__ int   g_off[MAXN];
__device__ int   g_bsum[256];        // raw per-block sums from scan1
__device__ int   g_bscan[256];       // exclusive-scanned (published by fill blk 0)
__device__ float g_dinv[MAXN];
__device__ int2  g_sedge[MAXE];      // (src, coef bits) sorted by dst
__device__ double g_sum1[DH], g_sq1[DH], g_sum2[DH], g_sq2[DH];
__device__ float g_A[DH], g_B[DH];
__device__ float g_Wc[DIN * DH];     // W_in@W1, permuted-chunked (see widx)
__device__ float g_bc[DH];           // b_in @ W1
__device__ float g_W2c[DH * DH];     // W2, permuted-chunked

// permuted-chunked weight index: thread cg (0..15) owns cols cg*4..cg*4+3;
// for sub-col jj the 16 lanes' 16B loads are CONTIGUOUS (256B / 2 lines).
__device__ __forceinline__ int widx(int k, int c) {
    return (k >> 2) * 256 + (c & 3) * 64 + (c >> 2) * 4 + (k & 3);
}

// ---------------- packed f32x2 helpers ----------------
#define FMA2(d,a,b)     asm("fma.rn.f32x2 %0, %1, %2, %0;" : "+l"(d) : "l"(a), "l"(b))
#define UNPACK2(l,h,s)  asm("mov.b64 {%0, %1}, %2;" : "=f"(l), "=f"(h) : "l"(s))
#define PACKF2(d,lo,hi) asm("mov.b64 %0, {%1, %2};" : "=l"(d) : "f"(lo), "f"(hi))

// ---------------- weight prep: Wc = W_in@W1 (permuted), bc, W2 (permuted) ----------------
__global__ void __launch_bounds__(256)
wcw2c_kernel(const float* __restrict__ Win, const float* __restrict__ W1,
             const float* __restrict__ b_in, const float* __restrict__ W2) {
    int t = threadIdx.x;
    if (blockIdx.x < 32) {
        __shared__ float sW1[DH * DH];
        for (int i = t; i < DH * DH; i += 256) sW1[i] = W1[i];
        __syncthreads();
        int o = blockIdx.x * 256 + t;            // 8192 outputs
        int i = o >> 6, j = o & 63;
        float s = 0.f;
#pragma unroll 16
        for (int k = 0; k < DH; k++) s += Win[i * DH + k] * sW1[k * DH + j];
        g_Wc[widx(i, j)] = s;
        if (o < DH) {
            float b = 0.f;
#pragma unroll 16
            for (int k = 0; k < DH; k++) b += b_in[k] * sW1[k * DH + j];
            g_bc[o] = b;
        }
    } else {
        int o = (blockIdx.x - 32) * 256 + t;     // 4096
        g_W2c[widx(o >> 6, o & 63)] = W2[o];
    }
}

// ---------------- small utility kernels ----------------
__global__ void zero_kernel(int n) {
    int i = blockIdx.x * blockDim.x + threadIdx.x;
    if (i < n) { g_degi[i] = 0; g_cur[i] = 0; }
    if (i < DH) {
        g_sum1[i] = 0.0; g_sq1[i] = 0.0;
        g_sum2[i] = 0.0; g_sq2[i] = 0.0;
    }
}

__global__ void deg_kernel(const int* __restrict__ dst, int E) {
    int e = blockIdx.x * blockDim.x + threadIdx.x;
    if (e < E) atomicAdd(&g_degi[dst[e]], 1);
}

// shuffle-based block scan -> exclusive offsets + raw block sums (+ dinv fused)
__global__ void __launch_bounds__(1024) scan1_kernel(int n) {
    __shared__ int wsum[32];
    int t = threadIdx.x;
    int lane = t & 31, wid = t >> 5;
    int i = blockIdx.x * 1024 + t;
    int v = (i < n) ? g_degi[i] : 0;
    int x = v;
#pragma unroll
    for (int off = 1; off < 32; off <<= 1) {
        int y = __shfl_up_sync(0xffffffffu, x, off);
        if (lane >= off) x += y;
    }
    if (lane == 31) wsum[wid] = x;
    __syncthreads();
    if (wid == 0) {
        int wv = wsum[lane];
        int wx = wv;
#pragma unroll
        for (int off = 1; off < 32; off <<= 1) {
            int y = __shfl_up_sync(0xffffffffu, wx, off);
            if (lane >= off) wx += y;
        }
        wsum[lane] = wx - wv;
    }
    __syncthreads();
    int incl = x + wsum[wid];
    if (i < n) {
        g_off[i] = incl - v;
        g_dinv[i] = rsqrtf((float)v + 1.0f);
    }
    if (t == 1023) g_bsum[blockIdx.x] = incl;
}

// fill (scan2 folded: every block scans the <=256 raw block sums in smem)
__global__ void __launch_bounds__(256)
fill_kernel(const int* __restrict__ src, const int* __restrict__ dst, int E, int nb) {
    __shared__ int s[256];
    int t = threadIdx.x;
    int v = (t < nb) ? g_bsum[t] : 0;
    s[t] = v; __syncthreads();
#pragma unroll
    for (int off = 1; off < 256; off <<= 1) {
        int tmp = (t >= off) ? s[t - off] : 0;
        __syncthreads();
        s[t] += tmp;
        __syncthreads();
    }
    int ex = s[t] - v;
    __syncthreads();
    s[t] = ex;
    if (blockIdx.x == 0 && t < nb) g_bscan[t] = ex;  // publish for agg
    __syncthreads();

    int e = blockIdx.x * 256 + t;
    if (e >= E) return;
    int d = dst[e], sc = src[e];
    int p = g_off[d] + s[d >> 10] + atomicAdd(&g_cur[d], 1);
    g_sedge[p] = make_int2(sc, __float_as_int(g_dinv[sc] * g_dinv[d]));
}

// ---------------- GEMM: g_xw[n,64] = X[n,K] @ W[K,64] ----------------
// No smem/syncs. Permuted-chunked weights: coalesced 256B weight loads AND
// adjacent per-thread cols -> STG.128 stores. FFMA2 lanes carry k-pairs.
// MODE 0: X = external arg, W = g_Wc, += g_bc.
// MODE 2: X = leaky(g_A*g_agg+g_B) (GraphNorm1 fused), W = g_W2c.
template<int K, int MODE>
__global__ void __launch_bounds__(256, 3)
gemm_kernel(const float* __restrict__ Xarg, int n) {
    const float* __restrict__ X = (MODE == 0) ? Xarg : g_agg;
    const float* __restrict__ Wp = (MODE == 0) ? g_Wc : g_W2c;
    const int tid = threadIdx.x;
    const int cg = tid & 15, rg = tid >> 4;
    const int r0 = blockIdx.x * 64 + rg * 4;
    const int c0 = cg * 4;

    bool ok[4];
#pragma unroll
    for (int i = 0; i < 4; i++) ok[i] = (r0 + i) < n;

    ull acc[4][4];
#pragma unroll
    for (int i = 0; i < 4; i++)
#pragma unroll
        for (int j = 0; j < 4; j++) acc[i][j] = 0ull;

#pragma unroll 4
    for (int kc = 0; kc < K / 4; kc++) {
        ulonglong2 wv[4];
#pragma unroll
        for (int jj = 0; jj < 4; jj++)
            wv[jj] = *(const ulonglong2*)(Wp + kc * 256 + jj * 64 + cg * 4);

        float4 Af, Bf;
        if (MODE == 2) {
            Af = *(const float4*)&g_A[kc * 4];
            Bf = *(const float4*)&g_B[kc * 4];
        }
#pragma unroll
        for (int i = 0; i < 4; i++) {
            ull x01 = 0ull, x23 = 0ull;
            if (ok[i]) {
                if (MODE == 0) {
                    ulonglong2 xv = *(const ulonglong2*)(X + (size_t)(r0 + i) * K + kc * 4);
                    x01 = xv.x; x23 = xv.y;
                } else {
                    float4 xf = *(const float4*)(X + (size_t)(r0 + i) * K + kc * 4);
                    xf.x = Af.x * xf.x + Bf.x; xf.x = fmaxf(xf.x, SLOPE * xf.x);
                    xf.y = Af.y * xf.y + Bf.y; xf.y = fmaxf(xf.y, SLOPE * xf.y);
                    xf.z = Af.z * xf.z + Bf.z; xf.z = fmaxf(xf.z, SLOPE * xf.z);
                    xf.w = Af.w * xf.w + Bf.w; xf.w = fmaxf(xf.w, SLOPE * xf.w);
                    PACKF2(x01, xf.x, xf.y);
                    PACKF2(x23, xf.z, xf.w);
                }
            }
            FMA2(acc[i][0], x01, wv[0].x); FMA2(acc[i][0], x23, wv[0].y);
            FMA2(acc[i][1], x01, wv[1].x); FMA2(acc[i][1], x23, wv[1].y);
            FMA2(acc[i][2], x01, wv[2].x); FMA2(acc[i][2], x23, wv[2].y);
            FMA2(acc[i][3], x01, wv[3].x); FMA2(acc[i][3], x23, wv[3].y);
        }
    }

    float4 bf = make_float4(0.f, 0.f, 0.f, 0.f);
    if (MODE == 0) bf = *(const float4*)&g_bc[c0];
#pragma unroll
    for (int i = 0; i < 4; i++) {
        if (!ok[i]) continue;
        float4 o;
        float lo, hi;
        UNPACK2(lo, hi, acc[i][0]); o.x = lo + hi + bf.x;
        UNPACK2(lo, hi, acc[i][1]); o.y = lo + hi + bf.y;
        UNPACK2(lo, hi, acc[i][2]); o.z = lo + hi + bf.z;
        UNPACK2(lo, hi, acc[i][3]); o.w = lo + hi + bf.w;
        *(float4*)&g_xw[(size_t)(r0 + i) * DH + c0] = o;
    }
}

// ---------------- CSR gather aggregation: one FULL warp per node ----------------
// lane owns cols {2*lane, 2*lane+1}; one LDG.64 row-load per edge; unroll 2.
__global__ void __launch_bounds__(256)
agg_kernel(const float* __restrict__ bias, int n) {
    int w = (blockIdx.x * 256 + threadIdx.x) >> 5;
    if (w >= n) return;
    int j2 = (threadIdx.x & 31) * 2;
    int start = g_off[w] + g_bscan[w >> 10];
    int end = start + g_degi[w];

    float a0 = 0.f, a1 = 0.f, b0 = 0.f, b1 = 0.f;
    int e = start;
    for (; e + 1 < end; e += 2) {
        int2 p0 = g_sedge[e];
        int2 p1 = g_sedge[e + 1];
        float2 v0 = *(const float2*)&g_xw[(size_t)p0.x * DH + j2];
        float2 v1 = *(const float2*)&g_xw[(size_t)p1.x * DH + j2];
        float c0 = __int_as_float(p0.y), c1 = __int_as_float(p1.y);
        a0 += c0 * v0.x; a1 += c0 * v0.y;
        b0 += c1 * v1.x; b1 += c1 * v1.y;
    }
    if (e < end) {
        int2 p = g_sedge[e];
        float2 v = *(const float2*)&g_xw[(size_t)p.x * DH + j2];
        float c = __int_as_float(p.y);
        a0 += c * v.x; a1 += c * v.y;
    }
    a0 += b0; a1 += b1;

    float d = g_dinv[w];
    float d2 = d * d;
    float2 xv = *(const float2*)&g_xw[(size_t)w * DH + j2];
    float2 bb = *(const float2*)&bias[j2];
    float2 o;
    o.x = a0 + d2 * xv.x + bb.x;
    o.y = a1 + d2 * xv.y + bb.y;
    *(float2*)&g_agg[(size_t)w * DH + j2] = o;
}

// ---------------- per-feature sum / sumsq reduction over nodes ----------------
template<int L>
__global__ void __launch_bounds__(256)
stats_kernel(int n) {
    int j = threadIdx.x & 63;
    int slot = threadIdx.x >> 6;
    int r = blockIdx.x * 4 + slot;
    int stride = gridDim.x * 4;
    float s = 0.f, q = 0.f;
    for (; r < n; r += stride) {
        float v = g_agg[(size_t)r * DH + j];
        s += v;
        q += v * v;
    }
    __shared__ float ss[4][DH];
    __shared__ float sq[4][DH];
    ss[slot][j] = s;
    sq[slot][j] = q;
    __syncthreads();
    if (threadIdx.x < DH) {
        double S = (double)ss[0][j] + ss[1][j] + ss[2][j] + ss[3][j];
        double Q = (double)sq[0][j] + sq[1][j] + sq[2][j] + sq[3][j];
        if (L == 1) { atomicAdd(&g_sum1[j], S); atomicAdd(&g_sq1[j], Q); }
        else        { atomicAdd(&g_sum2[j], S); atomicAdd(&g_sq2[j], Q); }
    }
}

template<int L>
__global__ void finalize_kernel(const float* __restrict__ alpha,
                                const float* __restrict__ gamma,
                                const float* __restrict__ beta, int n) {
    int j = threadIdx.x;
    if (j >= DH) return;
    double S = (L == 1) ? g_sum1[j] : g_sum2[j];
    double Q = (L == 1) ? g_sq1[j] : g_sq2[j];
    double m = S / (double)n;
    double a = (double)alpha[j];
    double var = Q / (double)n - 2.0 * a * m * m + a * a * m * m;
    float inv = rsqrtf((float)var + EPSN);
    float g = gamma[j] * inv;
    g_A[j] = g;
    g_B[j] = beta[j] - g * (float)(a * m);
}

// out = A*agg + B   (float4)
__global__ void __launch_bounds__(256)
norm_out_kernel(float* __restrict__ out, int total4) {
    int i = blockIdx.x * 256 + threadIdx.x;
    if (i >= total4) return;
    int j = (i * 4) & 63;
    float4 v = *(const float4*)&g_agg[(size_t)i * 4];
    float4 A = *(const float4*)&g_A[j];
    float4 B = *(const float4*)&g_B[j];
    v.x = A.x * v.x + B.x;
    v.y = A.y * v.y + B.y;
    v.z = A.z * v.z + B.z;
    v.w = A.w * v.w + B.w;
    *(float4*)&out[(size_t)i * 4] = v;
}

// ---------------- launcher ----------------
extern "C" void kernel_launch(void* const* d_in, const int* in_sizes, int n_in,
                              void* d_out, int out_size) {
    const float* x    = (const float*)d_in[0];
    const int*   ei   = (const int*)d_in[1];
    const float* W_in = (const float*)d_in[2];
    const float* b_in = (const float*)d_in[3];
    const float* W1   = (const float*)d_in[4];
    const float* b1   = (const float*)d_in[5];
    const float* a1   = (const float*)d_in[6];
    const float* gm1  = (const float*)d_in[7];
    const float* be1  = (const float*)d_in[8];
    const float* W2   = (const float*)d_in[9];
    const float* b2   = (const float*)d_in[10];
    const float* a2   = (const float*)d_in[11];
    const float* gm2  = (const float*)d_in[12];
    const float* be2  = (const float*)d_in[13];
    float* out = (float*)d_out;

    const int n = in_sizes[0] / DIN;
    const int E = in_sizes[1] / 2;
    const int* src = ei;
    const int* dst = ei + E;
    const int total4 = n * DH / 4;
    const int nb = (n + 1023) >> 10;
    const int gemm_blocks = (n + 63) / 64;

    // 0: fused weight prep
    wcw2c_kernel<<<48, 256>>>(W_in, W1, b_in, W2);
    // 1-2: degree
    zero_kernel<<<(n + 255) / 256, 256>>>(n);
    deg_kernel<<<(E + 255) / 256, 256>>>(dst, E);
    // 3: big GEMM (profile slot)
    gemm_kernel<DIN, 0><<<gemm_blocks, 256>>>(x, n);
    // 4-5: CSR build
    scan1_kernel<<<nb, 1024>>>(n);
    fill_kernel<<<(E + 255) / 256, 256>>>(src, dst, E, nb);
    // 6-8: layer 1 aggregate + stats + norm coefficients
    agg_kernel<<<(n + 7) / 8, 256>>>(b1, n);
    stats_kernel<1><<<1184, 256>>>(n);
    finalize_kernel<1><<<1, 64>>>(a1, gm1, be1, n);
    // 9: layer 2 GEMM with fused GraphNorm1+LeakyReLU input
    gemm_kernel<DH, 2><<<gemm_blocks, 256>>>(nullptr, n);
    // 10-12: layer 2 aggregate + stats + norm coefficients
    agg_kernel<<<(n + 7) / 8, 256>>>(b2, n);
    stats_kernel<2><<<1184, 256>>>(n);
    finalize_kernel<2><<<1, 64>>>(a2, gm2, be2, n);
    // 13: final output
    norm_out_kernel<<<(total4 + 255) / 256, 256>>>(out, total4);
}

// round 16
// speedup vs baseline: 2.1799x; 1.1744x over previous
#include <cuda_runtime.h>

#define DH 64
#define DIN 128
#define MAXN 100000
#define MAXE 1000000
#define EPSN 1e-5f
#define SLOPE 0.2f
typedef unsigned long long ull;

// ---------------- device scratch (no allocations allowed) ----------------
__device__ float g_xw[MAXN * DH];    // gemm output / gather source
__device__ float g_agg[MAXN * DH];   // aggregated output per layer
__device__ int   g_degi[MAXN];
__device__ int   g_cur[MAXN];
__device__ int   g_off[MAXN];
__device__ int   g_bsum[256];        // raw per-block sums from scan1
__device__ int   g_bscan[256];       // exclusive-scanned (published by fill blk 0)
__device__ float g_dinv[MAXN];
__device__ int2  g_sedge[MAXE];      // (src, coef bits) sorted by dst
__device__ float g_pS1[2048], g_pQ1[2048], g_pS2[2048], g_pQ2[2048]; // [32][64] staging
__device__ float g_A[DH], g_B[DH];
__device__ float g_Wc[DIN * DH];     // W_in@W1, permuted-chunked (see widx)
__device__ float g_bc[DH];           // b_in @ W1
__device__ float g_W2c[DH * DH];     // W2, permuted-chunked

// permuted-chunked weight index: thread cg (0..15) owns cols cg*4..cg*4+3;
// for sub-col jj the 16 lanes' 16B loads are CONTIGUOUS (256B / 2 lines).
__device__ __forceinline__ int widx(int k, int c) {
    return (k >> 2) * 256 + (c & 3) * 64 + (c >> 2) * 4 + (k & 3);
}

// ---------------- packed f32x2 helpers ----------------
#define FMA2(d,a,b)     asm("fma.rn.f32x2 %0, %1, %2, %0;" : "+l"(d) : "l"(a), "l"(b))
#define UNPACK2(l,h,s)  asm("mov.b64 {%0, %1}, %2;" : "=f"(l), "=f"(h) : "l"(s))
#define PACKF2(d,lo,hi) asm("mov.b64 %0, {%1, %2};" : "=l"(d) : "f"(lo), "f"(hi))

// ---------------- weight prep: Wc = W_in@W1 (permuted), bc, W2 (permuted) ----------------
__global__ void __launch_bounds__(256)
wcw2c_kernel(const float* __restrict__ Win, const float* __restrict__ W1,
             const float* __restrict__ b_in, const float* __restrict__ W2) {
    int t = threadIdx.x;
    if (blockIdx.x < 32) {
        __shared__ float sW1[DH * DH];
        for (int i = t; i < DH * DH; i += 256) sW1[i] = W1[i];
        __syncthreads();
        int o = blockIdx.x * 256 + t;            // 8192 outputs
        int i = o >> 6, j = o & 63;
        float s = 0.f;
#pragma unroll 16
        for (int k = 0; k < DH; k++) s += Win[i * DH + k] * sW1[k * DH + j];
        g_Wc[widx(i, j)] = s;
        if (o < DH) {
            float b = 0.f;
#pragma unroll 16
            for (int k = 0; k < DH; k++) b += b_in[k] * sW1[k * DH + j];
            g_bc[o] = b;
        }
    } else {
        int o = (blockIdx.x - 32) * 256 + t;     // 4096
        g_W2c[widx(o >> 6, o & 63)] = W2[o];
    }
}

// ---------------- small utility kernels ----------------
__global__ void zero_kernel(int n) {
    int i = blockIdx.x * blockDim.x + threadIdx.x;
    if (i < n) { g_degi[i] = 0; g_cur[i] = 0; }
    if (i < 2048) {
        g_pS1[i] = 0.f; g_pQ1[i] = 0.f;
        g_pS2[i] = 0.f; g_pQ2[i] = 0.f;
    }
}

__global__ void deg_kernel(const int* __restrict__ dst, int E) {
    int e = blockIdx.x * blockDim.x + threadIdx.x;
    if (e < E) atomicAdd(&g_degi[dst[e]], 1);
}

// shuffle-based block scan -> exclusive offsets + raw block sums (+ dinv fused)
__global__ void __launch_bounds__(1024) scan1_kernel(int n) {
    __shared__ int wsum[32];
    int t = threadIdx.x;
    int lane = t & 31, wid = t >> 5;
    int i = blockIdx.x * 1024 + t;
    int v = (i < n) ? g_degi[i] : 0;
    int x = v;
#pragma unroll
    for (int off = 1; off < 32; off <<= 1) {
        int y = __shfl_up_sync(0xffffffffu, x, off);
        if (lane >= off) x += y;
    }
    if (lane == 31) wsum[wid] = x;
    __syncthreads();
    if (wid == 0) {
        int wv = wsum[lane];
        int wx = wv;
#pragma unroll
        for (int off = 1; off < 32; off <<= 1) {
            int y = __shfl_up_sync(0xffffffffu, wx, off);
            if (lane >= off) wx += y;
        }
        wsum[lane] = wx - wv;
    }
    __syncthreads();
    int incl = x + wsum[wid];
    if (i < n) {
        g_off[i] = incl - v;
        g_dinv[i] = rsqrtf((float)v + 1.0f);
    }
    if (t == 1023) g_bsum[blockIdx.x] = incl;
}

// fill (scan2 folded: every block scans the <=256 raw block sums in smem)
__global__ void __launch_bounds__(256)
fill_kernel(const int* __restrict__ src, const int* __restrict__ dst, int E, int nb) {
    __shared__ int s[256];
    int t = threadIdx.x;
    int v = (t < nb) ? g_bsum[t] : 0;
    s[t] = v; __syncthreads();
#pragma unroll
    for (int off = 1; off < 256; off <<= 1) {
        int tmp = (t >= off) ? s[t - off] : 0;
        __syncthreads();
        s[t] += tmp;
        __syncthreads();
    }
    int ex = s[t] - v;
    __syncthreads();
    s[t] = ex;
    if (blockIdx.x == 0 && t < nb) g_bscan[t] = ex;  // publish for agg
    __syncthreads();

    int e = blockIdx.x * 256 + t;
    if (e >= E) return;
    int d = dst[e], sc = src[e];
    int p = g_off[d] + s[d >> 10] + atomicAdd(&g_cur[d], 1);
    g_sedge[p] = make_int2(sc, __float_as_int(g_dinv[sc] * g_dinv[d]));
}

// ---------------- GEMM: g_xw[n,64] = X[n,K] @ W[K,64] ----------------
// No smem/syncs. Permuted-chunked weights: coalesced 256B weight loads AND
// adjacent per-thread cols -> STG.128 stores. FFMA2 lanes carry k-pairs.
// MODE 0: X = external arg, W = g_Wc, += g_bc.
// MODE 2: X = leaky(g_A*g_agg+g_B) (GraphNorm1 fused), W = g_W2c.
template<int K, int MODE>
__global__ void __launch_bounds__(256, 3)
gemm_kernel(const float* __restrict__ Xarg, int n) {
    const float* __restrict__ X = (MODE == 0) ? Xarg : g_agg;
    const float* __restrict__ Wp = (MODE == 0) ? g_Wc : g_W2c;
    const int tid = threadIdx.x;
    const int cg = tid & 15, rg = tid >> 4;
    const int r0 = blockIdx.x * 64 + rg * 4;
    const int c0 = cg * 4;

    bool ok[4];
#pragma unroll
    for (int i = 0; i < 4; i++) ok[i] = (r0 + i) < n;

    ull acc[4][4];
#pragma unroll
    for (int i = 0; i < 4; i++)
#pragma unroll
        for (int j = 0; j < 4; j++) acc[i][j] = 0ull;

#pragma unroll 8
    for (int kc = 0; kc < K / 4; kc++) {
        ulonglong2 wv[4];
#pragma unroll
        for (int jj = 0; jj < 4; jj++)
            wv[jj] = *(const ulonglong2*)(Wp + kc * 256 + jj * 64 + cg * 4);

        float4 Af, Bf;
        if (MODE == 2) {
            Af = *(const float4*)&g_A[kc * 4];
            Bf = *(const float4*)&g_B[kc * 4];
        }
#pragma unroll
        for (int i = 0; i < 4; i++) {
            ull x01 = 0ull, x23 = 0ull;
            if (ok[i]) {
                if (MODE == 0) {
                    ulonglong2 xv = *(const ulonglong2*)(X + (size_t)(r0 + i) * K + kc * 4);
                    x01 = xv.x; x23 = xv.y;
                } else {
                    float4 xf = *(const float4*)(X + (size_t)(r0 + i) * K + kc * 4);
                    xf.x = Af.x * xf.x + Bf.x; xf.x = fmaxf(xf.x, SLOPE * xf.x);
                    xf.y = Af.y * xf.y + Bf.y; xf.y = fmaxf(xf.y, SLOPE * xf.y);
                    xf.z = Af.z * xf.z + Bf.z; xf.z = fmaxf(xf.z, SLOPE * xf.z);
                    xf.w = Af.w * xf.w + Bf.w; xf.w = fmaxf(xf.w, SLOPE * xf.w);
                    PACKF2(x01, xf.x, xf.y);
                    PACKF2(x23, xf.z, xf.w);
                }
            }
            FMA2(acc[i][0], x01, wv[0].x); FMA2(acc[i][0], x23, wv[0].y);
            FMA2(acc[i][1], x01, wv[1].x); FMA2(acc[i][1], x23, wv[1].y);
            FMA2(acc[i][2], x01, wv[2].x); FMA2(acc[i][2], x23, wv[2].y);
            FMA2(acc[i][3], x01, wv[3].x); FMA2(acc[i][3], x23, wv[3].y);
        }
    }

    float4 bf = make_float4(0.f, 0.f, 0.f, 0.f);
    if (MODE == 0) bf = *(const float4*)&g_bc[c0];
#pragma unroll
    for (int i = 0; i < 4; i++) {
        if (!ok[i]) continue;
        float4 o;
        float lo, hi;
        UNPACK2(lo, hi, acc[i][0]); o.x = lo + hi + bf.x;
        UNPACK2(lo, hi, acc[i][1]); o.y = lo + hi + bf.y;
        UNPACK2(lo, hi, acc[i][2]); o.z = lo + hi + bf.z;
        UNPACK2(lo, hi, acc[i][3]); o.w = lo + hi + bf.w;
        *(float4*)&g_xw[(size_t)(r0 + i) * DH + c0] = o;
    }
}

// ---------------- CSR gather aggregation + fused per-feature stats ----------------
// One full warp per node; lane owns cols {2l, 2l+1}; unroll 2 (deg~10).
// Block reduces its 8 nodes' outputs into spread float-atomic staging.
template<int L>
__global__ void __launch_bounds__(256)
agg_kernel(const float* __restrict__ bias, int n) {
    __shared__ float sS[8][DH];
    __shared__ float sQ[8][DH];
    int wid = threadIdx.x >> 5;
    int lane = threadIdx.x & 31;
    int w = blockIdx.x * 8 + wid;
    bool active = w < n;
    int j2 = lane * 2;

    float o0 = 0.f, o1 = 0.f;
    if (active) {
        int start = g_off[w] + g_bscan[w >> 10];
        int end = start + g_degi[w];
        float a0 = 0.f, a1 = 0.f, b0 = 0.f, b1 = 0.f;
        int e = start;
        for (; e + 1 < end; e += 2) {
            int2 p0 = g_sedge[e];
            int2 p1 = g_sedge[e + 1];
            float2 v0 = *(const float2*)&g_xw[(size_t)p0.x * DH + j2];
            float2 v1 = *(const float2*)&g_xw[(size_t)p1.x * DH + j2];
            float c0 = __int_as_float(p0.y), c1 = __int_as_float(p1.y);
            a0 += c0 * v0.x; a1 += c0 * v0.y;
            b0 += c1 * v1.x; b1 += c1 * v1.y;
        }
        if (e < end) {
            int2 p = g_sedge[e];
            float2 v = *(const float2*)&g_xw[(size_t)p.x * DH + j2];
            float c = __int_as_float(p.y);
            a0 += c * v.x; a1 += c * v.y;
        }
        a0 += b0; a1 += b1;

        float d = g_dinv[w];
        float dd = d * d;
        float2 xv = *(const float2*)&g_xw[(size_t)w * DH + j2];
        float2 bb = *(const float2*)&bias[j2];
        o0 = a0 + dd * xv.x + bb.x;
        o1 = a1 + dd * xv.y + bb.y;
        *(float2*)&g_agg[(size_t)w * DH + j2] = make_float2(o0, o1);
    }

    // fused stats: block partial sums -> spread staging
    sS[wid][j2] = o0;      sS[wid][j2 + 1] = o1;
    sQ[wid][j2] = o0 * o0; sQ[wid][j2 + 1] = o1 * o1;
    __syncthreads();
    if (threadIdx.x < DH) {
        int j = threadIdx.x;
        float s = 0.f, q = 0.f;
#pragma unroll
        for (int r = 0; r < 8; r++) { s += sS[r][j]; q += sQ[r][j]; }
        int slot = (blockIdx.x & 31) * DH + j;
        if (L == 1) { atomicAdd(&g_pS1[slot], s); atomicAdd(&g_pQ1[slot], q); }
        else        { atomicAdd(&g_pS2[slot], s); atomicAdd(&g_pQ2[slot], q); }
    }
}

// ---------------- fold GraphNorm into out = A*x + B ----------------
template<int L>
__global__ void finalize_kernel(const float* __restrict__ alpha,
                                const float* __restrict__ gamma,
                                const float* __restrict__ beta, int n) {
    int j = threadIdx.x;
    if (j >= DH) return;
    double S = 0.0, Q = 0.0;
    for (int k = 0; k < 32; k++) {
        if (L == 1) { S += (double)g_pS1[k * DH + j]; Q += (double)g_pQ1[k * DH + j]; }
        else        { S += (double)g_pS2[k * DH + j]; Q += (double)g_pQ2[k * DH + j]; }
    }
    double m = S / (double)n;
    double a = (double)alpha[j];
    double var = Q / (double)n - 2.0 * a * m * m + a * a * m * m;
    float inv = rsqrtf((float)var + EPSN);
    float g = gamma[j] * inv;
    g_A[j] = g;
    g_B[j] = beta[j] - g * (float)(a * m);
}

// out = A*agg + B   (float4)
__global__ void __launch_bounds__(256)
norm_out_kernel(float* __restrict__ out, int total4) {
    int i = blockIdx.x * 256 + threadIdx.x;
    if (i >= total4) return;
    int j = (i * 4) & 63;
    float4 v = *(const float4*)&g_agg[(size_t)i * 4];
    float4 A = *(const float4*)&g_A[j];
    float4 B = *(const float4*)&g_B[j];
    v.x = A.x * v.x + B.x;
    v.y = A.y * v.y + B.y;
    v.z = A.z * v.z + B.z;
    v.w = A.w * v.w + B.w;
    *(float4*)&out[(size_t)i * 4] = v;
}

// ---------------- launcher ----------------
extern "C" void kernel_launch(void* const* d_in, const int* in_sizes, int n_in,
                              void* d_out, int out_size) {
    const float* x    = (const float*)d_in[0];
    const int*   ei   = (const int*)d_in[1];
    const float* W_in = (const float*)d_in[2];
    const float* b_in = (const float*)d_in[3];
    const float* W1   = (const float*)d_in[4];
    const float* b1   = (const float*)d_in[5];
    const float* a1   = (const float*)d_in[6];
    const float* gm1  = (const float*)d_in[7];
    const float* be1  = (const float*)d_in[8];
    const float* W2   = (const float*)d_in[9];
    const float* b2   = (const float*)d_in[10];
    const float* a2   = (const float*)d_in[11];
    const float* gm2  = (const float*)d_in[12];
    const float* be2  = (const float*)d_in[13];
    float* out = (float*)d_out;

    const int n = in_sizes[0] / DIN;
    const int E = in_sizes[1] / 2;
    const int* src = ei;
    const int* dst = ei + E;
    const int total4 = n * DH / 4;
    const int nb = (n + 1023) >> 10;
    const int gemm_blocks = (n + 63) / 64;

    // fork a side stream inside capture: weight prep + big GEMM run
    // concurrently with the CSR build chain.
    cudaStream_t s2;
    cudaStreamCreateWithFlags(&s2, cudaStreamNonBlocking);
    cudaEvent_t evFork, evG;
    cudaEventCreateWithFlags(&evFork, cudaEventDisableTiming);
    cudaEventCreateWithFlags(&evG, cudaEventDisableTiming);

    // legacy-stream chain start (also establishes capture order)
    zero_kernel<<<(n + 255) / 256, 256>>>(n);
    cudaEventRecord(evFork, 0);
    cudaStreamWaitEvent(s2, evFork, 0);

    // side stream: weights -> big GEMM
    wcw2c_kernel<<<48, 256, 0, s2>>>(W_in, W1, b_in, W2);
    gemm_kernel<DIN, 0><<<gemm_blocks, 256, 0, s2>>>(x, n);
    cudaEventRecord(evG, s2);

    // legacy stream: CSR build
    deg_kernel<<<(E + 255) / 256, 256>>>(dst, E);
    scan1_kernel<<<nb, 1024>>>(n);
    fill_kernel<<<(E + 255) / 256, 256>>>(src, dst, E, nb);

    // join: layer 1 needs both g_xw (s2) and the CSR (legacy)
    cudaStreamWaitEvent(0, evG, 0);
    agg_kernel<1><<<(n + 7) / 8, 256>>>(b1, n);
    finalize_kernel<1><<<1, 64>>>(a1, gm1, be1, n);

    // layer 2 (GraphNorm1 + LeakyReLU fused into GEMM input)
    gemm_kernel<DH, 2><<<gemm_blocks, 256>>>(nullptr, n);
    agg_kernel<2><<<(n + 7) / 8, 256>>>(b2, n);
    finalize_kernel<2><<<1, 64>>>(a2, gm2, be2, n);
    norm_out_kernel<<<(total4 + 255) / 256, 256>>>(out, total4);
}